// round 15
// baseline (speedup 1.0000x reference)
#include <cuda_runtime.h>
#include <cuda_bf16.h>
#include <cstdint>

#define NN 50000
#define NE 800000
#define FDIM 128
#define NREL 4
#define BN_EPS 1e-5f
#define TM 128
#define TM2 64
#define NBLK2 ((NN + TM2 - 1) / TM2)  // 782
#define NT 256
#define NSEG (NREL * NN)              // 200000
#define CAP 32
#define MAXOVF 65536

#define STRD 136
#define TILE_B (TM * STRD * 2)        // 34816 B (128-row bf16 tile)
#define TILE_B64 (TM2 * STRD * 2)     // 17408 B (64-row bf16 tile)
// both GEMMs (M=64, 4-tile): Ah64, Al64, Bh(128-row), Bl(128-row)
#define SM2_AH 0
#define SM2_AL TILE_B64
#define SM2_BH (2 * TILE_B64)
#define SM2_BL (2 * TILE_B64 + TILE_B)
#define SM_TOTAL (2 * TILE_B64 + 2 * TILE_B)   // 104448 B -> 2 blocks/SM
#define EPI_LD 132

// scratch (uint4-typed: 16B alignment for cp.async)
__device__ uint4  g_h0h[((size_t)NSEG + TM) * FDIM / 8];
__device__ uint4  g_h0l[((size_t)NSEG + TM) * FDIM / 8];
__device__ uint4  g_xh[((size_t)NN + TM) * FDIM / 8];
__device__ uint4  g_xl[((size_t)NN + TM) * FDIM / 8];
__device__ float4 g_h1[(size_t)NSEG * FDIM / 4];
__device__ float  g_sum[NREL * FDIM];
__device__ float  g_sumsq[NREL * FDIM];
__device__ float4 g_scale[NREL * FDIM / 4];
__device__ float4 g_shift[NREL * FDIM / 4];
__device__ float4 g_bias[FDIM / 4];
__device__ uint4  g_wst[9][2][2048];
__device__ int    g_cnt[NSEG];
__device__ int    g_bkt[(size_t)NSEG * CAP];
__device__ int    g_ovf_cnt;
__device__ int2   g_ovf[MAXOVF];

// ---------------------------------------------------------------------------
__device__ __forceinline__ unsigned smem_u32(const void* p) {
    unsigned a;
    asm("{ .reg .u64 t; cvta.to.shared.u64 t, %1; cvt.u32.u64 %0, t; }"
        : "=r"(a) : "l"(p));
    return a;
}
__device__ __forceinline__ void cpa16(unsigned dst, const void* src) {
    asm volatile("cp.async.cg.shared.global [%0], [%1], 16;"
                 :: "r"(dst), "l"(src) : "memory");
}
#define CPA_COMMIT() asm volatile("cp.async.commit_group;" ::: "memory")
#define CPA_WAIT0()  asm volatile("cp.async.wait_group 0;" ::: "memory")

__device__ __forceinline__ void mma16816(float* c, const unsigned* a,
                                         unsigned b0, unsigned b1) {
    asm volatile(
        "mma.sync.aligned.m16n8k16.row.col.f32.bf16.bf16.f32 "
        "{%0,%1,%2,%3}, {%4,%5,%6,%7}, {%8,%9}, {%0,%1,%2,%3};"
        : "+f"(c[0]), "+f"(c[1]), "+f"(c[2]), "+f"(c[3])
        : "r"(a[0]), "r"(a[1]), "r"(a[2]), "r"(a[3]), "r"(b0), "r"(b1));
}
__device__ __forceinline__ void ldsm4(unsigned& r0, unsigned& r1,
                                      unsigned& r2, unsigned& r3, unsigned a) {
    asm volatile("ldmatrix.sync.aligned.m8n8.x4.shared.b16 {%0,%1,%2,%3}, [%4];"
                 : "=r"(r0), "=r"(r1), "=r"(r2), "=r"(r3) : "r"(a));
}

__device__ __forceinline__ void split_pack(float4 v, uint2& uh, uint2& ul) {
    __nv_bfloat16 h0 = __float2bfloat16_rn(v.x), h1 = __float2bfloat16_rn(v.y);
    __nv_bfloat16 h2 = __float2bfloat16_rn(v.z), h3 = __float2bfloat16_rn(v.w);
    __nv_bfloat16 g0 = __float2bfloat16_rn(v.x - __bfloat162float(h0));
    __nv_bfloat16 g1 = __float2bfloat16_rn(v.y - __bfloat162float(h1));
    __nv_bfloat16 g2 = __float2bfloat16_rn(v.z - __bfloat162float(h2));
    __nv_bfloat16 g3 = __float2bfloat16_rn(v.w - __bfloat162float(h3));
    uh.x = (unsigned)__bfloat16_as_ushort(h0) | ((unsigned)__bfloat16_as_ushort(h1) << 16);
    uh.y = (unsigned)__bfloat16_as_ushort(h2) | ((unsigned)__bfloat16_as_ushort(h3) << 16);
    ul.x = (unsigned)__bfloat16_as_ushort(g0) | ((unsigned)__bfloat16_as_ushort(g1) << 16);
    ul.y = (unsigned)__bfloat16_as_ushort(g2) | ((unsigned)__bfloat16_as_ushort(g3) << 16);
}

__device__ __forceinline__ void split_store2(char* smem, int row, int c0, float4 v) {
    unsigned off = (unsigned)(row * STRD + c0) * 2;
    uint2 uh, ul;
    split_pack(v, uh, ul);
    *(uint2*)(smem + SM2_AH + off) = uh;
    *(uint2*)(smem + SM2_AL + off) = ul;
}

// M=64 pass: 64x128x128, 8 warps as 2m x 4n (n-width 32)
__device__ __forceinline__ void mma_pass64(unsigned Asrc, unsigned Bsrc,
                                           float acc[2][4][4],
                                           int wm, int wn, int lid) {
    const int qt = lid >> 3, qr = lid & 7;
    const int arow = (qt & 1) ? 8 : 0;
    const int akk  = (qt & 2) ? 8 : 0;
    const int bn   = (qt & 2) ? 8 : 0;
    const int bkk  = (qt & 1) ? 8 : 0;
#pragma unroll 1
    for (int ks = 0; ks < 8; ks++) {
        const int k0 = ks * 16;
        unsigned a[2][4];
#pragma unroll
        for (int mf = 0; mf < 2; mf++) {
            int row = wm * 32 + mf * 16 + arow + qr;
            ldsm4(a[mf][0], a[mf][1], a[mf][2], a[mf][3],
                  Asrc + (unsigned)(row * STRD + k0 + akk) * 2);
        }
#pragma unroll
        for (int nfp = 0; nfp < 2; nfp++) {
            int n = wn * 32 + nfp * 16 + bn + qr;
            unsigned b0, b1, b2, b3;
            ldsm4(b0, b1, b2, b3, Bsrc + (unsigned)(n * STRD + k0 + bkk) * 2);
            mma16816(acc[0][nfp * 2],     a[0], b0, b1);
            mma16816(acc[1][nfp * 2],     a[1], b0, b1);
            mma16816(acc[0][nfp * 2 + 1], a[0], b2, b3);
            mma16816(acc[1][nfp * 2 + 1], a[1], b2, b3);
        }
    }
}

// 128-row tile copy (16 uint4 per row)
__device__ __forceinline__ void copy_t(unsigned sb_dst, const uint4* src, int tid) {
#pragma unroll
    for (int i = 0; i < 8; i++) {
        int idx = i * NT + tid;
        int n = idx >> 4, c = idx & 15;
        cpa16(sb_dst + n * STRD * 2 + c * 16, src + idx);
    }
}
// 64-row tile copy
__device__ __forceinline__ void copy_t64(unsigned sb_dst, const uint4* src, int tid) {
#pragma unroll
    for (int i = 0; i < 4; i++) {
        int idx = i * NT + tid;
        int n = idx >> 4, c = idx & 15;
        cpa16(sb_dst + n * STRD * 2 + c * 16, src + idx);
    }
}

// ---------------------------------------------------------------------------
__global__ void k_zero_cnt() {
    int i = blockIdx.x * blockDim.x + threadIdx.x;
    if (i < NSEG) g_cnt[i] = 0;
    if (i < NREL * FDIM) { g_sum[i] = 0.f; g_sumsq[i] = 0.f; }
    if (i == 0) g_ovf_cnt = 0;
}

// 4 edges per thread (coalesced stride) -> 4 independent atomic chains
__global__ void k_bucket(const int* __restrict__ edge_index,
                         const int* __restrict__ edge_type) {
    const int gid = blockIdx.x * blockDim.x + threadIdx.x;
    const int T = NE / 4;   // 200000
    if (gid >= T) return;
#pragma unroll
    for (int k = 0; k < 4; k++) {
        int e = gid + k * T;
        int src = edge_index[e];
        int dst = edge_index[NE + e];
        int rel = edge_type[e];
        if ((unsigned)src >= NN || (unsigned)dst >= NN || (unsigned)rel >= NREL)
            continue;
        int s = rel * NN + dst;
        int p = atomicAdd(&g_cnt[s], 1);
        if (p < CAP) {
            g_bkt[(size_t)s * CAP + p] = src;
        } else {
            int o = atomicAdd(&g_ovf_cnt, 1);
            if (o < MAXOVF) g_ovf[o] = make_int2(s, src);
        }
    }
}

__global__ void k_prepx(const float* __restrict__ x) {
    int i = blockIdx.x * blockDim.x + threadIdx.x;
    if (i >= NN * 32) return;
    int row = i >> 5, c4 = i & 31;
    float4 v = ((const float4*)x)[i];
    uint2 uh, ul;
    split_pack(v, uh, ul);
    *(uint2*)((unsigned short*)g_xh + (size_t)row * FDIM + c4 * 4) = uh;
    *(uint2*)((unsigned short*)g_xl + (size_t)row * FDIM + c4 * 4) = ul;
}

__global__ void __launch_bounds__(256) k_gather(const float* __restrict__ x) {
    int w = (blockIdx.x * blockDim.x + threadIdx.x) >> 5;
    if (w >= NSEG) return;
    const int q = threadIdx.x & 31;
    const float4* x4 = (const float4*)x;

    int cnt = g_cnt[w];
    int n = min(cnt, CAP);
    int myidx = g_bkt[(size_t)w * CAP + q];
    int node = w % NN;

    float4 acc = x4[(size_t)node * 32 + q];
#pragma unroll 4
    for (int j = 0; j < n; j++) {
        int s = __shfl_sync(0xFFFFFFFFu, myidx, j);
        float4 v = x4[(size_t)s * 32 + q];
        acc.x += v.x; acc.y += v.y; acc.z += v.z; acc.w += v.w;
    }
    if (cnt > CAP) {
        int total = min(g_ovf_cnt, MAXOVF);
        for (int o = 0; o < total; o++) {
            int2 ent = g_ovf[o];
            if (ent.x == w) {
                float4 v = x4[(size_t)ent.y * 32 + q];
                acc.x += v.x; acc.y += v.y; acc.z += v.z; acc.w += v.w;
            }
        }
    }
    uint2 uh, ul;
    split_pack(acc, uh, ul);
    *(uint2*)((unsigned short*)g_h0h + (size_t)w * FDIM + q * 4) = uh;
    *(uint2*)((unsigned short*)g_h0l + (size_t)w * FDIM + q * 4) = ul;
}

__global__ void k_prepw(const float* __restrict__ W1,
                        const float* __restrict__ W2,
                        const float* __restrict__ W_self) {
    int t = blockIdx.x;
    const float* src = (t < 4) ? W1 + t * FDIM * FDIM
                     : (t < 8) ? W2 + (t - 4) * FDIM * FDIM
                               : W_self;
    unsigned short* dh = (unsigned short*)g_wst[t][0];
    unsigned short* dl = (unsigned short*)g_wst[t][1];
    for (int idx = threadIdx.x; idx < FDIM * FDIM; idx += blockDim.x) {
        int k = idx >> 7;
        int n = idx & 127;
        float w = src[idx];
        __nv_bfloat16 hi = __float2bfloat16_rn(w);
        __nv_bfloat16 lo = __float2bfloat16_rn(w - __bfloat162float(hi));
        dh[n * FDIM + k] = __bfloat16_as_ushort(hi);
        dl[n * FDIM + k] = __bfloat16_as_ushort(lo);
    }
}

__global__ void k_bn(const float* __restrict__ gamma, const float* __restrict__ beta,
                     const float* __restrict__ b_self, const float* __restrict__ b2) {
    int i = threadIdx.x;
    if (i < NREL * FDIM) {
        const float invN = 1.f / (float)NN;
        float mean = g_sum[i] * invN;
        float var = g_sumsq[i] * invN - mean * mean;
        float sc = gamma[i] * rsqrtf(var + BN_EPS);
        ((float*)g_scale)[i] = sc;
        ((float*)g_shift)[i] = beta[i] - mean * sc;
    }
    if (i < FDIM) {
        float b = b_self[i];
#pragma unroll
        for (int r = 0; r < NREL; r++) b += b2[r * FDIM + i];
        ((float*)g_bias)[i] = b;
    }
}

// ---------------------------------------------------------------------------
// GEMM1 (M=64, 4-tile, no mid-stage stall): h1[r] = h0[r] @ W1[r] + b1[r]
// grid: (NBLK2, NREL) = 3128 blocks; fused BN stats
// ---------------------------------------------------------------------------
__global__ void __launch_bounds__(NT, 2) k_gemm1(const float* __restrict__ b1) {
    extern __shared__ char smem[];
    const unsigned sb = smem_u32(smem);
    const int tid = threadIdx.x;
    const int wid = tid >> 5, lid = tid & 31;
    const int wm = wid & 1, wn = wid >> 1;   // 2m x 4n
    const int g = lid >> 2, tg = lid & 3;
    const int r = blockIdx.y;
    const int n0 = blockIdx.x * TM2;
    const int valid = min(NN - n0, TM2);

    const uint4* Ah = (const uint4*)((const unsigned short*)g_h0h +
                                     (size_t)(r * NN + n0) * FDIM);
    const uint4* Al = (const uint4*)((const unsigned short*)g_h0l +
                                     (size_t)(r * NN + n0) * FDIM);
    copy_t64(sb + SM2_AH, Ah, tid);
    copy_t64(sb + SM2_AL, Al, tid);
    copy_t(sb + SM2_BH, g_wst[r][0], tid);
    copy_t(sb + SM2_BL, g_wst[r][1], tid);
    CPA_COMMIT();
    CPA_WAIT0();
    __syncthreads();

    float acc[2][4][4];
#pragma unroll
    for (int mf = 0; mf < 2; mf++)
#pragma unroll
        for (int nf = 0; nf < 4; nf++)
#pragma unroll
            for (int j = 0; j < 4; j++) acc[mf][nf][j] = 0.f;

    mma_pass64(sb + SM2_AH, sb + SM2_BH, acc, wm, wn, lid);
    mma_pass64(sb + SM2_AL, sb + SM2_BH, acc, wm, wn, lid);
    mma_pass64(sb + SM2_AH, sb + SM2_BL, acc, wm, wn, lid);
    __syncthreads();

    // epilogue staging: 64 x 128 fp32 at stride EPI_LD (33792 B over A-tiles)
    float* E = (float*)smem;
#pragma unroll
    for (int mf = 0; mf < 2; mf++)
#pragma unroll
        for (int nf = 0; nf < 4; nf++) {
            int row = wm * 32 + mf * 16 + g;
            int col = wn * 32 + nf * 8 + tg * 2;
            *(float2*)(E + row * EPI_LD + col) =
                make_float2(acc[mf][nf][0], acc[mf][nf][1]);
            *(float2*)(E + (row + 8) * EPI_LD + col) =
                make_float2(acc[mf][nf][2], acc[mf][nf][3]);
        }
    __syncthreads();

    const int c4 = tid & 31, rg = tid >> 5;
    float4 bias = *(const float4*)(b1 + r * FDIM + c4 * 4);
    float s4[4] = {0, 0, 0, 0}, q4[4] = {0, 0, 0, 0};
    float* Hout = (float*)g_h1 + (size_t)r * NN * FDIM;
#pragma unroll
    for (int i = 0; i < 8; i++) {
        int row = i * 8 + rg;
        if (row < valid) {
            float4 v = *(float4*)(E + row * EPI_LD + c4 * 4);
            v.x += bias.x; v.y += bias.y; v.z += bias.z; v.w += bias.w;
            s4[0] += v.x; q4[0] += v.x * v.x;
            s4[1] += v.y; q4[1] += v.y * v.y;
            s4[2] += v.z; q4[2] += v.z * v.z;
            s4[3] += v.w; q4[3] += v.w * v.w;
            *(float4*)(Hout + (size_t)(n0 + row) * FDIM + c4 * 4) = v;
        }
    }
    // stats reduce in B-tile region (disjoint from E)
    float* redS = (float*)(smem + SM2_BH);
    float* redQ = redS + 8 * FDIM;
#pragma unroll
    for (int j = 0; j < 4; j++) {
        redS[rg * FDIM + c4 * 4 + j] = s4[j];
        redQ[rg * FDIM + c4 * 4 + j] = q4[j];
    }
    __syncthreads();
    if (tid < FDIM) {
        float S = 0.f, Q = 0.f;
#pragma unroll
        for (int p = 0; p < 8; p++) { S += redS[p * FDIM + tid]; Q += redQ[p * FDIM + tid]; }
        atomicAdd(&g_sum[r * FDIM + tid], S);
        atomicAdd(&g_sumsq[r * FDIM + tid], Q);
    }
}

// ---------------------------------------------------------------------------
// GEMM2 (K=640, M=64, 4-tile): out = sum_r relu(bn(h1[r])) @ W2[r] + x@W_self + b
// ---------------------------------------------------------------------------
__global__ void __launch_bounds__(NT, 2) k_gemm2(float* __restrict__ out) {
    extern __shared__ char smem[];
    const unsigned sb = smem_u32(smem);
    const int tid = threadIdx.x;
    const int wid = tid >> 5, lid = tid & 31;
    const int wm = wid & 1, wn = wid >> 1;   // 2m x 4n
    const int g = lid >> 2, tg = lid & 3;
    const int n0 = blockIdx.x * TM2;
    const int valid = min(NN - n0, TM2);

    float acc[2][4][4];
#pragma unroll
    for (int mf = 0; mf < 2; mf++)
#pragma unroll
        for (int nf = 0; nf < 4; nf++)
#pragma unroll
            for (int j = 0; j < 4; j++) acc[mf][nf][j] = 0.f;

    for (int r = 0; r < NREL + 1; r++) {
        __syncthreads();
        const int t = (r < NREL) ? 4 + r : 8;

        copy_t(sb + SM2_BH, g_wst[t][0], tid);
        copy_t(sb + SM2_BL, g_wst[t][1], tid);

        if (r < NREL) {
            CPA_COMMIT();
            const float* H = (const float*)g_h1 + (size_t)r * NN * FDIM;
#pragma unroll
            for (int i = 0; i < 8; i++) {
                int idx = i * NT + tid;
                int row = idx >> 5, c4 = idx & 31;
                float4 v = make_float4(0.f, 0.f, 0.f, 0.f);
                if (row < valid) {
                    v = ((const float4*)(H + (size_t)(n0 + row) * FDIM))[c4];
                    float4 sc = g_scale[r * (FDIM / 4) + c4];
                    float4 sh = g_shift[r * (FDIM / 4) + c4];
                    v.x = fmaxf(v.x * sc.x + sh.x, 0.f);
                    v.y = fmaxf(v.y * sc.y + sh.y, 0.f);
                    v.z = fmaxf(v.z * sc.z + sh.z, 0.f);
                    v.w = fmaxf(v.w * sc.w + sh.w, 0.f);
                }
                split_store2(smem, row, c4 * 4, v);
            }
        } else {
            const uint4* Xh = (const uint4*)((const unsigned short*)g_xh +
                                             (size_t)n0 * FDIM);
            const uint4* Xl = (const uint4*)((const unsigned short*)g_xl +
                                             (size_t)n0 * FDIM);
            copy_t64(sb + SM2_AH, Xh, tid);
            copy_t64(sb + SM2_AL, Xl, tid);
            CPA_COMMIT();
        }
        CPA_WAIT0();
        __syncthreads();

        mma_pass64(sb + SM2_AH, sb + SM2_BH, acc, wm, wn, lid);
        mma_pass64(sb + SM2_AL, sb + SM2_BH, acc, wm, wn, lid);
        mma_pass64(sb + SM2_AH, sb + SM2_BL, acc, wm, wn, lid);
    }
    __syncthreads();

    float* E = (float*)smem;
#pragma unroll
    for (int mf = 0; mf < 2; mf++)
#pragma unroll
        for (int nf = 0; nf < 4; nf++) {
            int row = wm * 32 + mf * 16 + g;
            int col = wn * 32 + nf * 8 + tg * 2;
            *(float2*)(E + row * EPI_LD + col) =
                make_float2(acc[mf][nf][0], acc[mf][nf][1]);
            *(float2*)(E + (row + 8) * EPI_LD + col) =
                make_float2(acc[mf][nf][2], acc[mf][nf][3]);
        }
    __syncthreads();

    const int c4 = tid & 31, rg = tid >> 5;
    float4 bias = g_bias[c4];
#pragma unroll
    for (int i = 0; i < 8; i++) {
        int row = i * 8 + rg;
        if (row < valid) {
            float4 v = *(float4*)(E + row * EPI_LD + c4 * 4);
            v.x += bias.x; v.y += bias.y; v.z += bias.z; v.w += bias.w;
            *(float4*)(out + (size_t)(n0 + row) * FDIM + c4 * 4) = v;
        }
    }
}

extern "C" void kernel_launch(void* const* d_in, const int* in_sizes, int n_in,
                              void* d_out, int out_size) {
    const float* x          = (const float*)d_in[0];
    const int*   edge_index = (const int*)d_in[1];   // int32 (JAX x64 disabled)
    const int*   edge_type  = (const int*)d_in[2];
    const float* W_self     = (const float*)d_in[3];
    const float* b_self     = (const float*)d_in[4];
    const float* W1         = (const float*)d_in[5];
    const float* b1         = (const float*)d_in[6];
    const float* gamma      = (const float*)d_in[7];
    const float* beta       = (const float*)d_in[8];
    const float* W2         = (const float*)d_in[9];
    const float* b2         = (const float*)d_in[10];
    float* out = (float*)d_out;

    cudaFuncSetAttribute(k_gemm1, cudaFuncAttributeMaxDynamicSharedMemorySize, SM_TOTAL);
    cudaFuncSetAttribute(k_gemm2, cudaFuncAttributeMaxDynamicSharedMemorySize, SM_TOTAL);

    k_zero_cnt<<<(NSEG + 255) / 256, 256>>>();
    k_prepw<<<9, 256>>>(W1, W2, W_self);
    k_prepx<<<(NN * 32 + 255) / 256, 256>>>(x);
    k_bucket<<<(NE / 4 + 255) / 256, 256>>>(edge_index, edge_type);
    k_gather<<<(NSEG * 32 + 255) / 256, 256>>>(x);
    dim3 g1(NBLK2, NREL);
    k_gemm1<<<g1, NT, SM_TOTAL>>>(b1);
    k_bn<<<1, 512>>>(gamma, beta, b_self, b2);
    k_gemm2<<<NBLK2, NT, SM_TOTAL>>>(out);
}

// round 16
// speedup vs baseline: 1.1727x; 1.1727x over previous
#include <cuda_runtime.h>
#include <cuda_bf16.h>
#include <cstdint>

#define NN 50000
#define NE 800000
#define FDIM 128
#define NREL 4
#define BN_EPS 1e-5f
#define TM 128
#define NBLK ((NN + TM - 1) / TM)     // 391
#define TM2 64
#define NBLK2 ((NN + TM2 - 1) / TM2)  // 782
#define NT 256
#define NSEG (NREL * NN)              // 200000
#define CAP 32
#define MAXOVF 65536

#define STRD 136
#define TILE_B (TM * STRD * 2)        // 34816 B (128-row bf16 tile)
#define TILE_B64 (TM2 * STRD * 2)     // 17408 B (64-row bf16 tile)
// gemm1 (3-buffer, full tiles): T0=Ah, T1=Al/Bl, T2=Bh
#define SM_AH 0
#define SM_AL TILE_B
#define SM_BH (2 * TILE_B)
// gemm2 (M=64, 4-tile): Ah64, Al64, Bh(128-row), Bl(128-row)
#define SM2_AH 0
#define SM2_AL TILE_B64
#define SM2_BH (2 * TILE_B64)
#define SM2_BL (2 * TILE_B64 + TILE_B)
#define SM_TOTAL (3 * TILE_B)         // 104448 B -> 2 blocks/SM (both kernels)
#define EPI_LD 132

// merged-prep grid split
#define PREP_Z 782                       // zero blocks
#define PREP_W 576                       // 9*16384/256 weight blocks
#define PREP_X 6250                      // NN*32/256 x-split blocks
#define PREP_TOTAL (PREP_Z + PREP_W + PREP_X)

// scratch (uint4-typed: 16B alignment for cp.async)
__device__ uint4  g_h0h[((size_t)NSEG + TM) * FDIM / 8];
__device__ uint4  g_h0l[((size_t)NSEG + TM) * FDIM / 8];
__device__ uint4  g_xh[((size_t)NN + TM) * FDIM / 8];
__device__ uint4  g_xl[((size_t)NN + TM) * FDIM / 8];
__device__ float4 g_h1[(size_t)NSEG * FDIM / 4];
__device__ float  g_sum[NREL * FDIM];
__device__ float  g_sumsq[NREL * FDIM];
__device__ float4 g_scale[NREL * FDIM / 4];
__device__ float4 g_shift[NREL * FDIM / 4];
__device__ float4 g_bias[FDIM / 4];
__device__ uint4  g_wst[9][2][2048];
__device__ int    g_cnt[NSEG];
__device__ int    g_bkt[(size_t)NSEG * CAP];
__device__ int    g_ovf_cnt;
__device__ int2   g_ovf[MAXOVF];

// ---------------------------------------------------------------------------
__device__ __forceinline__ unsigned smem_u32(const void* p) {
    unsigned a;
    asm("{ .reg .u64 t; cvta.to.shared.u64 t, %1; cvt.u32.u64 %0, t; }"
        : "=r"(a) : "l"(p));
    return a;
}
__device__ __forceinline__ void cpa16(unsigned dst, const void* src) {
    asm volatile("cp.async.cg.shared.global [%0], [%1], 16;"
                 :: "r"(dst), "l"(src) : "memory");
}
#define CPA_COMMIT() asm volatile("cp.async.commit_group;" ::: "memory")
#define CPA_WAIT0()  asm volatile("cp.async.wait_group 0;" ::: "memory")

__device__ __forceinline__ void mma16816(float* c, const unsigned* a,
                                         unsigned b0, unsigned b1) {
    asm volatile(
        "mma.sync.aligned.m16n8k16.row.col.f32.bf16.bf16.f32 "
        "{%0,%1,%2,%3}, {%4,%5,%6,%7}, {%8,%9}, {%0,%1,%2,%3};"
        : "+f"(c[0]), "+f"(c[1]), "+f"(c[2]), "+f"(c[3])
        : "r"(a[0]), "r"(a[1]), "r"(a[2]), "r"(a[3]), "r"(b0), "r"(b1));
}
__device__ __forceinline__ void ldsm4(unsigned& r0, unsigned& r1,
                                      unsigned& r2, unsigned& r3, unsigned a) {
    asm volatile("ldmatrix.sync.aligned.m8n8.x4.shared.b16 {%0,%1,%2,%3}, [%4];"
                 : "=r"(r0), "=r"(r1), "=r"(r2), "=r"(r3) : "r"(a));
}

__device__ __forceinline__ void split_pack(float4 v, uint2& uh, uint2& ul) {
    __nv_bfloat16 h0 = __float2bfloat16_rn(v.x), h1 = __float2bfloat16_rn(v.y);
    __nv_bfloat16 h2 = __float2bfloat16_rn(v.z), h3 = __float2bfloat16_rn(v.w);
    __nv_bfloat16 g0 = __float2bfloat16_rn(v.x - __bfloat162float(h0));
    __nv_bfloat16 g1 = __float2bfloat16_rn(v.y - __bfloat162float(h1));
    __nv_bfloat16 g2 = __float2bfloat16_rn(v.z - __bfloat162float(h2));
    __nv_bfloat16 g3 = __float2bfloat16_rn(v.w - __bfloat162float(h3));
    uh.x = (unsigned)__bfloat16_as_ushort(h0) | ((unsigned)__bfloat16_as_ushort(h1) << 16);
    uh.y = (unsigned)__bfloat16_as_ushort(h2) | ((unsigned)__bfloat16_as_ushort(h3) << 16);
    ul.x = (unsigned)__bfloat16_as_ushort(g0) | ((unsigned)__bfloat16_as_ushort(g1) << 16);
    ul.y = (unsigned)__bfloat16_as_ushort(g2) | ((unsigned)__bfloat16_as_ushort(g3) << 16);
}

__device__ __forceinline__ void split_store2(char* smem, int row, int c0, float4 v) {
    unsigned off = (unsigned)(row * STRD + c0) * 2;
    uint2 uh, ul;
    split_pack(v, uh, ul);
    *(uint2*)(smem + SM2_AH + off) = uh;
    *(uint2*)(smem + SM2_AL + off) = ul;
}

// full pass (gemm1): 128x128x128, 8 warps as 4m x 2n (n-width 64)
__device__ __forceinline__ void mma_pass(unsigned Asrc, unsigned Bsrc,
                                         float acc[2][8][4],
                                         int wm, int wn, int lid) {
    const int qt = lid >> 3, qr = lid & 7;
    const int arow = (qt & 1) ? 8 : 0;
    const int akk  = (qt & 2) ? 8 : 0;
    const int bn   = (qt & 2) ? 8 : 0;
    const int bkk  = (qt & 1) ? 8 : 0;
#pragma unroll 1
    for (int ks = 0; ks < 8; ks++) {
        const int k0 = ks * 16;
        unsigned a[2][4];
#pragma unroll
        for (int mf = 0; mf < 2; mf++) {
            int row = wm * 32 + mf * 16 + arow + qr;
            ldsm4(a[mf][0], a[mf][1], a[mf][2], a[mf][3],
                  Asrc + (unsigned)(row * STRD + k0 + akk) * 2);
        }
#pragma unroll
        for (int nfp = 0; nfp < 4; nfp++) {
            int n = wn * 64 + nfp * 16 + bn + qr;
            unsigned b0, b1, b2, b3;
            ldsm4(b0, b1, b2, b3, Bsrc + (unsigned)(n * STRD + k0 + bkk) * 2);
            mma16816(acc[0][nfp * 2],     a[0], b0, b1);
            mma16816(acc[1][nfp * 2],     a[1], b0, b1);
            mma16816(acc[0][nfp * 2 + 1], a[0], b2, b3);
            mma16816(acc[1][nfp * 2 + 1], a[1], b2, b3);
        }
    }
}

// M=64 pass (gemm2): 64x128x128, 8 warps as 2m x 4n (n-width 32)
__device__ __forceinline__ void mma_pass64(unsigned Asrc, unsigned Bsrc,
                                           float acc[2][4][4],
                                           int wm, int wn, int lid) {
    const int qt = lid >> 3, qr = lid & 7;
    const int arow = (qt & 1) ? 8 : 0;
    const int akk  = (qt & 2) ? 8 : 0;
    const int bn   = (qt & 2) ? 8 : 0;
    const int bkk  = (qt & 1) ? 8 : 0;
#pragma unroll 1
    for (int ks = 0; ks < 8; ks++) {
        const int k0 = ks * 16;
        unsigned a[2][4];
#pragma unroll
        for (int mf = 0; mf < 2; mf++) {
            int row = wm * 32 + mf * 16 + arow + qr;
            ldsm4(a[mf][0], a[mf][1], a[mf][2], a[mf][3],
                  Asrc + (unsigned)(row * STRD + k0 + akk) * 2);
        }
#pragma unroll
        for (int nfp = 0; nfp < 2; nfp++) {
            int n = wn * 32 + nfp * 16 + bn + qr;
            unsigned b0, b1, b2, b3;
            ldsm4(b0, b1, b2, b3, Bsrc + (unsigned)(n * STRD + k0 + bkk) * 2);
            mma16816(acc[0][nfp * 2],     a[0], b0, b1);
            mma16816(acc[1][nfp * 2],     a[1], b0, b1);
            mma16816(acc[0][nfp * 2 + 1], a[0], b2, b3);
            mma16816(acc[1][nfp * 2 + 1], a[1], b2, b3);
        }
    }
}

__device__ __forceinline__ void copy_t(unsigned sb_dst, const uint4* src, int tid) {
#pragma unroll
    for (int i = 0; i < 8; i++) {
        int idx = i * NT + tid;
        int n = idx >> 4, c = idx & 15;
        cpa16(sb_dst + n * STRD * 2 + c * 16, src + idx);
    }
}
__device__ __forceinline__ void copy_t64(unsigned sb_dst, const uint4* src, int tid) {
#pragma unroll
    for (int i = 0; i < 4; i++) {
        int idx = i * NT + tid;
        int n = idx >> 4, c = idx & 15;
        cpa16(sb_dst + n * STRD * 2 + c * 16, src + idx);
    }
}

// ---------------------------------------------------------------------------
// merged prep: zero counters/stats | weight split | x split (one launch)
// ---------------------------------------------------------------------------
__global__ void k_prep(const float* __restrict__ W1,
                       const float* __restrict__ W2,
                       const float* __restrict__ W_self,
                       const float* __restrict__ x) {
    const int bid = blockIdx.x;
    const int tid = threadIdx.x;
    if (bid < PREP_Z) {
        int i = bid * NT + tid;
        if (i < NSEG) g_cnt[i] = 0;
        if (i < NREL * FDIM) { g_sum[i] = 0.f; g_sumsq[i] = 0.f; }
        if (i == 0) g_ovf_cnt = 0;
    } else if (bid < PREP_Z + PREP_W) {
        int j = (bid - PREP_Z) * NT + tid;   // < 9*16384
        int t = j >> 14;
        int idx = j & 16383;
        const float* src = (t < 4) ? W1 + t * FDIM * FDIM
                         : (t < 8) ? W2 + (t - 4) * FDIM * FDIM
                                   : W_self;
        int k = idx >> 7;
        int n = idx & 127;
        float w = src[idx];
        __nv_bfloat16 hi = __float2bfloat16_rn(w);
        __nv_bfloat16 lo = __float2bfloat16_rn(w - __bfloat162float(hi));
        ((unsigned short*)g_wst[t][0])[n * FDIM + k] = __bfloat16_as_ushort(hi);
        ((unsigned short*)g_wst[t][1])[n * FDIM + k] = __bfloat16_as_ushort(lo);
    } else {
        int i = (bid - PREP_Z - PREP_W) * NT + tid;
        if (i >= NN * 32) return;
        int row = i >> 5, c4 = i & 31;
        float4 v = ((const float4*)x)[i];
        uint2 uh, ul;
        split_pack(v, uh, ul);
        *(uint2*)((unsigned short*)g_xh + (size_t)row * FDIM + c4 * 4) = uh;
        *(uint2*)((unsigned short*)g_xl + (size_t)row * FDIM + c4 * 4) = ul;
    }
}

// 4 edges per thread (coalesced stride) -> 4 independent atomic chains
__global__ void k_bucket(const int* __restrict__ edge_index,
                         const int* __restrict__ edge_type) {
    const int gid = blockIdx.x * blockDim.x + threadIdx.x;
    const int T = NE / 4;   // 200000
    if (gid >= T) return;
#pragma unroll
    for (int k = 0; k < 4; k++) {
        int e = gid + k * T;
        int src = edge_index[e];
        int dst = edge_index[NE + e];
        int rel = edge_type[e];
        if ((unsigned)src >= NN || (unsigned)dst >= NN || (unsigned)rel >= NREL)
            continue;
        int s = rel * NN + dst;
        int p = atomicAdd(&g_cnt[s], 1);
        if (p < CAP) {
            g_bkt[(size_t)s * CAP + p] = src;
        } else {
            int o = atomicAdd(&g_ovf_cnt, 1);
            if (o < MAXOVF) g_ovf[o] = make_int2(s, src);
        }
    }
}

__global__ void __launch_bounds__(256) k_gather(const float* __restrict__ x) {
    int w = (blockIdx.x * blockDim.x + threadIdx.x) >> 5;
    if (w >= NSEG) return;
    const int q = threadIdx.x & 31;
    const float4* x4 = (const float4*)x;

    int cnt = g_cnt[w];
    int n = min(cnt, CAP);
    int myidx = g_bkt[(size_t)w * CAP + q];
    int node = w % NN;

    float4 acc = x4[(size_t)node * 32 + q];
#pragma unroll 4
    for (int j = 0; j < n; j++) {
        int s = __shfl_sync(0xFFFFFFFFu, myidx, j);
        float4 v = x4[(size_t)s * 32 + q];
        acc.x += v.x; acc.y += v.y; acc.z += v.z; acc.w += v.w;
    }
    if (cnt > CAP) {
        int total = min(g_ovf_cnt, MAXOVF);
        for (int o = 0; o < total; o++) {
            int2 ent = g_ovf[o];
            if (ent.x == w) {
                float4 v = x4[(size_t)ent.y * 32 + q];
                acc.x += v.x; acc.y += v.y; acc.z += v.z; acc.w += v.w;
            }
        }
    }
    uint2 uh, ul;
    split_pack(acc, uh, ul);
    *(uint2*)((unsigned short*)g_h0h + (size_t)w * FDIM + q * 4) = uh;
    *(uint2*)((unsigned short*)g_h0l + (size_t)w * FDIM + q * 4) = ul;
}

__global__ void k_bn(const float* __restrict__ gamma, const float* __restrict__ beta,
                     const float* __restrict__ b_self, const float* __restrict__ b2) {
    int i = threadIdx.x;
    if (i < NREL * FDIM) {
        const float invN = 1.f / (float)NN;
        float mean = g_sum[i] * invN;
        float var = g_sumsq[i] * invN - mean * mean;
        float sc = gamma[i] * rsqrtf(var + BN_EPS);
        ((float*)g_scale)[i] = sc;
        ((float*)g_shift)[i] = beta[i] - mean * sc;
    }
    if (i < FDIM) {
        float b = b_self[i];
#pragma unroll
        for (int r = 0; r < NREL; r++) b += b2[r * FDIM + i];
        ((float*)g_bias)[i] = b;
    }
}

// ---------------------------------------------------------------------------
// GEMM1 (M=128, 3-buffer): all tiles via cp.async, fused BN stats
// ---------------------------------------------------------------------------
__global__ void __launch_bounds__(NT, 2) k_gemm1(const float* __restrict__ b1) {
    extern __shared__ char smem[];
    const unsigned sb = smem_u32(smem);
    const int tid = threadIdx.x;
    const int wid = tid >> 5, lid = tid & 31;
    const int wm = wid & 3, wn = wid >> 2;
    const int g = lid >> 2, tg = lid & 3;
    const int r = blockIdx.y;
    const int n0 = blockIdx.x * TM;
    const int valid = min(NN - n0, TM);

    const uint4* Ah = (const uint4*)((const unsigned short*)g_h0h +
                                     (size_t)(r * NN + n0) * FDIM);
    const uint4* Al = (const uint4*)((const unsigned short*)g_h0l +
                                     (size_t)(r * NN + n0) * FDIM);
    copy_t(sb + SM_AH, Ah, tid);
    copy_t(sb + SM_AL, Al, tid);
    copy_t(sb + SM_BH, g_wst[r][0], tid);
    CPA_COMMIT();
    CPA_WAIT0();
    __syncthreads();

    float acc[2][8][4];
#pragma unroll
    for (int mf = 0; mf < 2; mf++)
#pragma unroll
        for (int nf = 0; nf < 8; nf++)
#pragma unroll
            for (int j = 0; j < 4; j++) acc[mf][nf][j] = 0.f;

    mma_pass(sb + SM_AH, sb + SM_BH, acc, wm, wn, lid);
    mma_pass(sb + SM_AL, sb + SM_BH, acc, wm, wn, lid);
    __syncthreads();
    copy_t(sb + SM_AL, g_wst[r][1], tid);   // Bl over Al
    CPA_COMMIT();
    CPA_WAIT0();
    __syncthreads();
    mma_pass(sb + SM_AH, sb + SM_AL, acc, wm, wn, lid);
    __syncthreads();

    float* E = (float*)smem;
#pragma unroll
    for (int mf = 0; mf < 2; mf++)
#pragma unroll
        for (int nf = 0; nf < 8; nf++) {
            int row = wm * 32 + mf * 16 + g;
            int col = wn * 64 + nf * 8 + tg * 2;
            *(float2*)(E + row * EPI_LD + col) =
                make_float2(acc[mf][nf][0], acc[mf][nf][1]);
            *(float2*)(E + (row + 8) * EPI_LD + col) =
                make_float2(acc[mf][nf][2], acc[mf][nf][3]);
        }
    __syncthreads();

    const int c4 = tid & 31, rg = tid >> 5;
    float4 bias = *(const float4*)(b1 + r * FDIM + c4 * 4);
    float s4[4] = {0, 0, 0, 0}, q4[4] = {0, 0, 0, 0};
    float* Hout = (float*)g_h1 + (size_t)r * NN * FDIM;
#pragma unroll
    for (int i = 0; i < 16; i++) {
        int row = i * 8 + rg;
        if (row < valid) {
            float4 v = *(float4*)(E + row * EPI_LD + c4 * 4);
            v.x += bias.x; v.y += bias.y; v.z += bias.z; v.w += bias.w;
            s4[0] += v.x; q4[0] += v.x * v.x;
            s4[1] += v.y; q4[1] += v.y * v.y;
            s4[2] += v.z; q4[2] += v.z * v.z;
            s4[3] += v.w; q4[3] += v.w * v.w;
            *(float4*)(Hout + (size_t)(n0 + row) * FDIM + c4 * 4) = v;
        }
    }
    float* redS = (float*)(smem + SM_BH);
    float* redQ = redS + 8 * FDIM;
#pragma unroll
    for (int j = 0; j < 4; j++) {
        redS[rg * FDIM + c4 * 4 + j] = s4[j];
        redQ[rg * FDIM + c4 * 4 + j] = q4[j];
    }
    __syncthreads();
    if (tid < FDIM) {
        float S = 0.f, Q = 0.f;
#pragma unroll
        for (int p = 0; p < 8; p++) { S += redS[p * FDIM + tid]; Q += redQ[p * FDIM + tid]; }
        atomicAdd(&g_sum[r * FDIM + tid], S);
        atomicAdd(&g_sumsq[r * FDIM + tid], Q);
    }
}

// ---------------------------------------------------------------------------
// GEMM2 (K=640, M=64 per block, all 4 tiles resident, no mid-stage stall)
// ---------------------------------------------------------------------------
__global__ void __launch_bounds__(NT, 2) k_gemm2(float* __restrict__ out) {
    extern __shared__ char smem[];
    const unsigned sb = smem_u32(smem);
    const int tid = threadIdx.x;
    const int wid = tid >> 5, lid = tid & 31;
    const int wm = wid & 1, wn = wid >> 1;   // 2m x 4n
    const int g = lid >> 2, tg = lid & 3;
    const int n0 = blockIdx.x * TM2;
    const int valid = min(NN - n0, TM2);

    float acc[2][4][4];
#pragma unroll
    for (int mf = 0; mf < 2; mf++)
#pragma unroll
        for (int nf = 0; nf < 4; nf++)
#pragma unroll
            for (int j = 0; j < 4; j++) acc[mf][nf][j] = 0.f;

    for (int r = 0; r < NREL + 1; r++) {
        __syncthreads();
        const int t = (r < NREL) ? 4 + r : 8;

        copy_t(sb + SM2_BH, g_wst[t][0], tid);
        copy_t(sb + SM2_BL, g_wst[t][1], tid);

        if (r < NREL) {
            CPA_COMMIT();
            const float* H = (const float*)g_h1 + (size_t)r * NN * FDIM;
#pragma unroll
            for (int i = 0; i < 8; i++) {
                int idx = i * NT + tid;
                int row = idx >> 5, c4 = idx & 31;
                float4 v = make_float4(0.f, 0.f, 0.f, 0.f);
                if (row < valid) {
                    v = ((const float4*)(H + (size_t)(n0 + row) * FDIM))[c4];
                    float4 sc = g_scale[r * (FDIM / 4) + c4];
                    float4 sh = g_shift[r * (FDIM / 4) + c4];
                    v.x = fmaxf(v.x * sc.x + sh.x, 0.f);
                    v.y = fmaxf(v.y * sc.y + sh.y, 0.f);
                    v.z = fmaxf(v.z * sc.z + sh.z, 0.f);
                    v.w = fmaxf(v.w * sc.w + sh.w, 0.f);
                }
                split_store2(smem, row, c4 * 4, v);
            }
        } else {
            const uint4* Xh = (const uint4*)((const unsigned short*)g_xh +
                                             (size_t)n0 * FDIM);
            const uint4* Xl = (const uint4*)((const unsigned short*)g_xl +
                                             (size_t)n0 * FDIM);
            copy_t64(sb + SM2_AH, Xh, tid);
            copy_t64(sb + SM2_AL, Xl, tid);
            CPA_COMMIT();
        }
        CPA_WAIT0();
        __syncthreads();

        mma_pass64(sb + SM2_AH, sb + SM2_BH, acc, wm, wn, lid);
        mma_pass64(sb + SM2_AL, sb + SM2_BH, acc, wm, wn, lid);
        mma_pass64(sb + SM2_AH, sb + SM2_BL, acc, wm, wn, lid);
    }
    __syncthreads();

    float* E = (float*)smem;
#pragma unroll
    for (int mf = 0; mf < 2; mf++)
#pragma unroll
        for (int nf = 0; nf < 4; nf++) {
            int row = wm * 32 + mf * 16 + g;
            int col = wn * 32 + nf * 8 + tg * 2;
            *(float2*)(E + row * EPI_LD + col) =
                make_float2(acc[mf][nf][0], acc[mf][nf][1]);
            *(float2*)(E + (row + 8) * EPI_LD + col) =
                make_float2(acc[mf][nf][2], acc[mf][nf][3]);
        }
    __syncthreads();

    const int c4 = tid & 31, rg = tid >> 5;
    float4 bias = g_bias[c4];
#pragma unroll
    for (int i = 0; i < 8; i++) {
        int row = i * 8 + rg;
        if (row < valid) {
            float4 v = *(float4*)(E + row * EPI_LD + c4 * 4);
            v.x += bias.x; v.y += bias.y; v.z += bias.z; v.w += bias.w;
            *(float4*)(out + (size_t)(n0 + row) * FDIM + c4 * 4) = v;
        }
    }
}

extern "C" void kernel_launch(void* const* d_in, const int* in_sizes, int n_in,
                              void* d_out, int out_size) {
    const float* x          = (const float*)d_in[0];
    const int*   edge_index = (const int*)d_in[1];   // int32 (JAX x64 disabled)
    const int*   edge_type  = (const int*)d_in[2];
    const float* W_self     = (const float*)d_in[3];
    const float* b_self     = (const float*)d_in[4];
    const float* W1         = (const float*)d_in[5];
    const float* b1         = (const float*)d_in[6];
    const float* gamma      = (const float*)d_in[7];
    const float* beta       = (const float*)d_in[8];
    const float* W2         = (const float*)d_in[9];
    const float* b2         = (const float*)d_in[10];
    float* out = (float*)d_out;

    cudaFuncSetAttribute(k_gemm1, cudaFuncAttributeMaxDynamicSharedMemorySize, SM_TOTAL);
    cudaFuncSetAttribute(k_gemm2, cudaFuncAttributeMaxDynamicSharedMemorySize, SM_TOTAL);

    k_prep<<<PREP_TOTAL, NT>>>(W1, W2, W_self, x);
    k_bucket<<<(NE / 4 + 255) / 256, 256>>>(edge_index, edge_type);
    k_gather<<<(NSEG * 32 + 255) / 256, 256>>>(x);
    dim3 g1(NBLK, NREL);
    k_gemm1<<<g1, NT, SM_TOTAL>>>(b1);
    k_bn<<<1, 512>>>(gamma, beta, b_self, b2);
    k_gemm2<<<NBLK2, NT, SM_TOTAL>>>(out);
}

// round 17
// speedup vs baseline: 1.4051x; 1.1982x over previous
#include <cuda_runtime.h>
#include <cuda_fp16.h>
#include <cstdint>

#define NN 50000
#define NE 800000
#define FDIM 128
#define NREL 4
#define BN_EPS 1e-5f
#define TM 128
#define NBLK ((NN + TM - 1) / TM)     // 391
#define TM2 64
#define NBLK2 ((NN + TM2 - 1) / TM2)  // 782
#define NT 256
#define NSEG (NREL * NN)              // 200000
#define CAP 32
#define MAXOVF 65536

#define STRD 136
#define TILE_B (TM * STRD * 2)        // 34816 B (128-row fp16 tile)
#define TILE_B64 (TM2 * STRD * 2)     // 17408 B (64-row fp16 tile)
// gemm1: A(128-row) + Bh + Bl, all resident -> no mid-stage stall
#define SM_A  0
#define SM_BH TILE_B
#define SM_BL (2 * TILE_B)
#define SM_TOTAL1 (3 * TILE_B)        // 104448 B -> 2 blocks/SM
// gemm2 (M=64): A64 + Bh + Bl
#define SM2_A  0
#define SM2_BH TILE_B64
#define SM2_BL (TILE_B64 + TILE_B)
#define SM_TOTAL2 (TILE_B64 + 2 * TILE_B)   // 87040 B -> 2 blocks/SM
#define EPI_LD 132

// merged-prep grid split
#define PREP_Z 782
#define PREP_W 576                       // 9*16384/256
#define PREP_X 6250                      // NN*32/256
#define PREP_TOTAL (PREP_Z + PREP_W + PREP_X)

// scratch (uint4-typed: 16B alignment for cp.async)
__device__ uint4  g_h0h[((size_t)NSEG + TM) * FDIM / 8];   // h0 fp16 rows
__device__ uint4  g_xh[((size_t)NN + TM) * FDIM / 8];      // x fp16 rows
__device__ float4 g_h1[(size_t)NSEG * FDIM / 4];
__device__ float  g_sum[NREL * FDIM];
__device__ float  g_sumsq[NREL * FDIM];
__device__ float4 g_scale[NREL * FDIM / 4];
__device__ float4 g_shift[NREL * FDIM / 4];
__device__ float4 g_bias[FDIM / 4];
__device__ uint4  g_wst[9][2][2048];                       // fp16 hi / lo
__device__ int    g_cnt[NSEG];
__device__ int    g_bkt[(size_t)NSEG * CAP];
__device__ int    g_ovf_cnt;
__device__ int2   g_ovf[MAXOVF];

// ---------------------------------------------------------------------------
__device__ __forceinline__ unsigned smem_u32(const void* p) {
    unsigned a;
    asm("{ .reg .u64 t; cvta.to.shared.u64 t, %1; cvt.u32.u64 %0, t; }"
        : "=r"(a) : "l"(p));
    return a;
}
__device__ __forceinline__ void cpa16(unsigned dst, const void* src) {
    asm volatile("cp.async.cg.shared.global [%0], [%1], 16;"
                 :: "r"(dst), "l"(src) : "memory");
}
#define CPA_COMMIT() asm volatile("cp.async.commit_group;" ::: "memory")
#define CPA_WAIT0()  asm volatile("cp.async.wait_group 0;" ::: "memory")

__device__ __forceinline__ void mma16816(float* c, const unsigned* a,
                                         unsigned b0, unsigned b1) {
    asm volatile(
        "mma.sync.aligned.m16n8k16.row.col.f32.f16.f16.f32 "
        "{%0,%1,%2,%3}, {%4,%5,%6,%7}, {%8,%9}, {%0,%1,%2,%3};"
        : "+f"(c[0]), "+f"(c[1]), "+f"(c[2]), "+f"(c[3])
        : "r"(a[0]), "r"(a[1]), "r"(a[2]), "r"(a[3]), "r"(b0), "r"(b1));
}
__device__ __forceinline__ void ldsm4(unsigned& r0, unsigned& r1,
                                      unsigned& r2, unsigned& r3, unsigned a) {
    asm volatile("ldmatrix.sync.aligned.m8n8.x4.shared.b16 {%0,%1,%2,%3}, [%4];"
                 : "=r"(r0), "=r"(r1), "=r"(r2), "=r"(r3) : "r"(a));
}

// pack fp32x4 -> fp16x4 (single precision level; residual dropped by design)
__device__ __forceinline__ uint2 pack_f16(float4 v) {
    __half h0 = __float2half_rn(v.x), h1 = __float2half_rn(v.y);
    __half h2 = __float2half_rn(v.z), h3 = __float2half_rn(v.w);
    uint2 u;
    u.x = (unsigned)__half_as_ushort(h0) | ((unsigned)__half_as_ushort(h1) << 16);
    u.y = (unsigned)__half_as_ushort(h2) | ((unsigned)__half_as_ushort(h3) << 16);
    return u;
}

// full pass (gemm1): 128x128x128, 8 warps as 4m x 2n (n-width 64)
__device__ __forceinline__ void mma_pass(unsigned Asrc, unsigned Bsrc,
                                         float acc[2][8][4],
                                         int wm, int wn, int lid) {
    const int qt = lid >> 3, qr = lid & 7;
    const int arow = (qt & 1) ? 8 : 0;
    const int akk  = (qt & 2) ? 8 : 0;
    const int bn   = (qt & 2) ? 8 : 0;
    const int bkk  = (qt & 1) ? 8 : 0;
#pragma unroll 1
    for (int ks = 0; ks < 8; ks++) {
        const int k0 = ks * 16;
        unsigned a[2][4];
#pragma unroll
        for (int mf = 0; mf < 2; mf++) {
            int row = wm * 32 + mf * 16 + arow + qr;
            ldsm4(a[mf][0], a[mf][1], a[mf][2], a[mf][3],
                  Asrc + (unsigned)(row * STRD + k0 + akk) * 2);
        }
#pragma unroll
        for (int nfp = 0; nfp < 4; nfp++) {
            int n = wn * 64 + nfp * 16 + bn + qr;
            unsigned b0, b1, b2, b3;
            ldsm4(b0, b1, b2, b3, Bsrc + (unsigned)(n * STRD + k0 + bkk) * 2);
            mma16816(acc[0][nfp * 2],     a[0], b0, b1);
            mma16816(acc[1][nfp * 2],     a[1], b0, b1);
            mma16816(acc[0][nfp * 2 + 1], a[0], b2, b3);
            mma16816(acc[1][nfp * 2 + 1], a[1], b2, b3);
        }
    }
}

// M=64 pass (gemm2): 64x128x128, 8 warps as 2m x 4n (n-width 32)
__device__ __forceinline__ void mma_pass64(unsigned Asrc, unsigned Bsrc,
                                           float acc[2][4][4],
                                           int wm, int wn, int lid) {
    const int qt = lid >> 3, qr = lid & 7;
    const int arow = (qt & 1) ? 8 : 0;
    const int akk  = (qt & 2) ? 8 : 0;
    const int bn   = (qt & 2) ? 8 : 0;
    const int bkk  = (qt & 1) ? 8 : 0;
#pragma unroll 1
    for (int ks = 0; ks < 8; ks++) {
        const int k0 = ks * 16;
        unsigned a[2][4];
#pragma unroll
        for (int mf = 0; mf < 2; mf++) {
            int row = wm * 32 + mf * 16 + arow + qr;
            ldsm4(a[mf][0], a[mf][1], a[mf][2], a[mf][3],
                  Asrc + (unsigned)(row * STRD + k0 + akk) * 2);
        }
#pragma unroll
        for (int nfp = 0; nfp < 2; nfp++) {
            int n = wn * 32 + nfp * 16 + bn + qr;
            unsigned b0, b1, b2, b3;
            ldsm4(b0, b1, b2, b3, Bsrc + (unsigned)(n * STRD + k0 + bkk) * 2);
            mma16816(acc[0][nfp * 2],     a[0], b0, b1);
            mma16816(acc[1][nfp * 2],     a[1], b0, b1);
            mma16816(acc[0][nfp * 2 + 1], a[0], b2, b3);
            mma16816(acc[1][nfp * 2 + 1], a[1], b2, b3);
        }
    }
}

__device__ __forceinline__ void copy_t(unsigned sb_dst, const uint4* src, int tid) {
#pragma unroll
    for (int i = 0; i < 8; i++) {
        int idx = i * NT + tid;
        int n = idx >> 4, c = idx & 15;
        cpa16(sb_dst + n * STRD * 2 + c * 16, src + idx);
    }
}
__device__ __forceinline__ void copy_t64(unsigned sb_dst, const uint4* src, int tid) {
#pragma unroll
    for (int i = 0; i < 4; i++) {
        int idx = i * NT + tid;
        int n = idx >> 4, c = idx & 15;
        cpa16(sb_dst + n * STRD * 2 + c * 16, src + idx);
    }
}

// ---------------------------------------------------------------------------
// merged prep: zero counters/stats | weight split (fp16 hi/lo) | x fp16
// ---------------------------------------------------------------------------
__global__ void k_prep(const float* __restrict__ W1,
                       const float* __restrict__ W2,
                       const float* __restrict__ W_self,
                       const float* __restrict__ x) {
    const int bid = blockIdx.x;
    const int tid = threadIdx.x;
    if (bid < PREP_Z) {
        int i = bid * NT + tid;
        if (i < NSEG) g_cnt[i] = 0;
        if (i < NREL * FDIM) { g_sum[i] = 0.f; g_sumsq[i] = 0.f; }
        if (i == 0) g_ovf_cnt = 0;
    } else if (bid < PREP_Z + PREP_W) {
        int j = (bid - PREP_Z) * NT + tid;   // < 9*16384
        int t = j >> 14;
        int idx = j & 16383;
        const float* src = (t < 4) ? W1 + t * FDIM * FDIM
                         : (t < 8) ? W2 + (t - 4) * FDIM * FDIM
                                   : W_self;
        int k = idx >> 7;
        int n = idx & 127;
        float w = src[idx];
        __half hi = __float2half_rn(w);
        __half lo = __float2half_rn(w - __half2float(hi));
        ((unsigned short*)g_wst[t][0])[n * FDIM + k] = __half_as_ushort(hi);
        ((unsigned short*)g_wst[t][1])[n * FDIM + k] = __half_as_ushort(lo);
    } else {
        int i = (bid - PREP_Z - PREP_W) * NT + tid;
        if (i >= NN * 32) return;
        int row = i >> 5, c4 = i & 31;
        float4 v = ((const float4*)x)[i];
        *(uint2*)((unsigned short*)g_xh + (size_t)row * FDIM + c4 * 4) = pack_f16(v);
    }
}

// 4 edges per thread (coalesced stride)
__global__ void k_bucket(const int* __restrict__ edge_index,
                         const int* __restrict__ edge_type) {
    const int gid = blockIdx.x * blockDim.x + threadIdx.x;
    const int T = NE / 4;
    if (gid >= T) return;
#pragma unroll
    for (int k = 0; k < 4; k++) {
        int e = gid + k * T;
        int src = edge_index[e];
        int dst = edge_index[NE + e];
        int rel = edge_type[e];
        if ((unsigned)src >= NN || (unsigned)dst >= NN || (unsigned)rel >= NREL)
            continue;
        int s = rel * NN + dst;
        int p = atomicAdd(&g_cnt[s], 1);
        if (p < CAP) {
            g_bkt[(size_t)s * CAP + p] = src;
        } else {
            int o = atomicAdd(&g_ovf_cnt, 1);
            if (o < MAXOVF) g_ovf[o] = make_int2(s, src);
        }
    }
}

__global__ void __launch_bounds__(256) k_gather(const float* __restrict__ x) {
    int w = (blockIdx.x * blockDim.x + threadIdx.x) >> 5;
    if (w >= NSEG) return;
    const int q = threadIdx.x & 31;
    const float4* x4 = (const float4*)x;

    int cnt = g_cnt[w];
    int n = min(cnt, CAP);
    int myidx = g_bkt[(size_t)w * CAP + q];
    int node = w % NN;

    float4 acc = x4[(size_t)node * 32 + q];
#pragma unroll 4
    for (int j = 0; j < n; j++) {
        int s = __shfl_sync(0xFFFFFFFFu, myidx, j);
        float4 v = x4[(size_t)s * 32 + q];
        acc.x += v.x; acc.y += v.y; acc.z += v.z; acc.w += v.w;
    }
    if (cnt > CAP) {
        int total = min(g_ovf_cnt, MAXOVF);
        for (int o = 0; o < total; o++) {
            int2 ent = g_ovf[o];
            if (ent.x == w) {
                float4 v = x4[(size_t)ent.y * 32 + q];
                acc.x += v.x; acc.y += v.y; acc.z += v.z; acc.w += v.w;
            }
        }
    }
    *(uint2*)((unsigned short*)g_h0h + (size_t)w * FDIM + q * 4) = pack_f16(acc);
}

__global__ void k_bn(const float* __restrict__ gamma, const float* __restrict__ beta,
                     const float* __restrict__ b_self, const float* __restrict__ b2) {
    int i = threadIdx.x;
    if (i < NREL * FDIM) {
        const float invN = 1.f / (float)NN;
        float mean = g_sum[i] * invN;
        float var = g_sumsq[i] * invN - mean * mean;
        float sc = gamma[i] * rsqrtf(var + BN_EPS);
        ((float*)g_scale)[i] = sc;
        ((float*)g_shift)[i] = beta[i] - mean * sc;
    }
    if (i < FDIM) {
        float b = b_self[i];
#pragma unroll
        for (int r = 0; r < NREL; r++) b += b2[r * FDIM + i];
        ((float*)g_bias)[i] = b;
    }
}

// ---------------------------------------------------------------------------
// GEMM1 (M=128, fp16-A 2-pass): h1[r] = h0[r] @ W1[r] + b1[r]; fused BN stats
// A + Bh + Bl all resident -> single load phase, 2 mma passes
// ---------------------------------------------------------------------------
__global__ void __launch_bounds__(NT, 2) k_gemm1(const float* __restrict__ b1) {
    extern __shared__ char smem[];
    const unsigned sb = smem_u32(smem);
    const int tid = threadIdx.x;
    const int wid = tid >> 5, lid = tid & 31;
    const int wm = wid & 3, wn = wid >> 2;
    const int g = lid >> 2, tg = lid & 3;
    const int r = blockIdx.y;
    const int n0 = blockIdx.x * TM;
    const int valid = min(NN - n0, TM);

    const uint4* Ah = (const uint4*)((const unsigned short*)g_h0h +
                                     (size_t)(r * NN + n0) * FDIM);
    copy_t(sb + SM_A, Ah, tid);
    copy_t(sb + SM_BH, g_wst[r][0], tid);
    copy_t(sb + SM_BL, g_wst[r][1], tid);
    CPA_COMMIT();
    CPA_WAIT0();
    __syncthreads();

    float acc[2][8][4];
#pragma unroll
    for (int mf = 0; mf < 2; mf++)
#pragma unroll
        for (int nf = 0; nf < 8; nf++)
#pragma unroll
            for (int j = 0; j < 4; j++) acc[mf][nf][j] = 0.f;

    mma_pass(sb + SM_A, sb + SM_BH, acc, wm, wn, lid);
    mma_pass(sb + SM_A, sb + SM_BL, acc, wm, wn, lid);
    __syncthreads();

    float* E = (float*)smem;   // 128 x EPI_LD fp32 (67584 B over A+Bh)
#pragma unroll
    for (int mf = 0; mf < 2; mf++)
#pragma unroll
        for (int nf = 0; nf < 8; nf++) {
            int row = wm * 32 + mf * 16 + g;
            int col = wn * 64 + nf * 8 + tg * 2;
            *(float2*)(E + row * EPI_LD + col) =
                make_float2(acc[mf][nf][0], acc[mf][nf][1]);
            *(float2*)(E + (row + 8) * EPI_LD + col) =
                make_float2(acc[mf][nf][2], acc[mf][nf][3]);
        }
    __syncthreads();

    const int c4 = tid & 31, rg = tid >> 5;
    float4 bias = *(const float4*)(b1 + r * FDIM + c4 * 4);
    float s4[4] = {0, 0, 0, 0}, q4[4] = {0, 0, 0, 0};
    float* Hout = (float*)g_h1 + (size_t)r * NN * FDIM;
#pragma unroll
    for (int i = 0; i < 16; i++) {
        int row = i * 8 + rg;
        if (row < valid) {
            float4 v = *(float4*)(E + row * EPI_LD + c4 * 4);
            v.x += bias.x; v.y += bias.y; v.z += bias.z; v.w += bias.w;
            s4[0] += v.x; q4[0] += v.x * v.x;
            s4[1] += v.y; q4[1] += v.y * v.y;
            s4[2] += v.z; q4[2] += v.z * v.z;
            s4[3] += v.w; q4[3] += v.w * v.w;
            *(float4*)(Hout + (size_t)(n0 + row) * FDIM + c4 * 4) = v;
        }
    }
    // stats reduce in Bl region (disjoint from E)
    float* redS = (float*)(smem + SM_BL);
    float* redQ = redS + 8 * FDIM;
#pragma unroll
    for (int j = 0; j < 4; j++) {
        redS[rg * FDIM + c4 * 4 + j] = s4[j];
        redQ[rg * FDIM + c4 * 4 + j] = q4[j];
    }
    __syncthreads();
    if (tid < FDIM) {
        float S = 0.f, Q = 0.f;
#pragma unroll
        for (int p = 0; p < 8; p++) { S += redS[p * FDIM + tid]; Q += redQ[p * FDIM + tid]; }
        atomicAdd(&g_sum[r * FDIM + tid], S);
        atomicAdd(&g_sumsq[r * FDIM + tid], Q);
    }
}

// ---------------------------------------------------------------------------
// GEMM2 (K=640, M=64, fp16-A 2-pass): out = sum_r relu(bn(h1[r]))@W2[r]
//                                           + x@W_self + bias
// ---------------------------------------------------------------------------
__global__ void __launch_bounds__(NT, 2) k_gemm2(float* __restrict__ out) {
    extern __shared__ char smem[];
    const unsigned sb = smem_u32(smem);
    const int tid = threadIdx.x;
    const int wid = tid >> 5, lid = tid & 31;
    const int wm = wid & 1, wn = wid >> 1;   // 2m x 4n
    const int g = lid >> 2, tg = lid & 3;
    const int n0 = blockIdx.x * TM2;
    const int valid = min(NN - n0, TM2);

    float acc[2][4][4];
#pragma unroll
    for (int mf = 0; mf < 2; mf++)
#pragma unroll
        for (int nf = 0; nf < 4; nf++)
#pragma unroll
            for (int j = 0; j < 4; j++) acc[mf][nf][j] = 0.f;

    for (int r = 0; r < NREL + 1; r++) {
        __syncthreads();
        const int t = (r < NREL) ? 4 + r : 8;

        copy_t(sb + SM2_BH, g_wst[t][0], tid);
        copy_t(sb + SM2_BL, g_wst[t][1], tid);

        if (r < NREL) {
            CPA_COMMIT();
            const float* H = (const float*)g_h1 + (size_t)r * NN * FDIM;
#pragma unroll
            for (int i = 0; i < 8; i++) {
                int idx = i * NT + tid;
                int row = idx >> 5, c4 = idx & 31;
                float4 v = make_float4(0.f, 0.f, 0.f, 0.f);
                if (row < valid) {
                    v = ((const float4*)(H + (size_t)(n0 + row) * FDIM))[c4];
                    float4 sc = g_scale[r * (FDIM / 4) + c4];
                    float4 sh = g_shift[r * (FDIM / 4) + c4];
                    v.x = fmaxf(v.x * sc.x + sh.x, 0.f);
                    v.y = fmaxf(v.y * sc.y + sh.y, 0.f);
                    v.z = fmaxf(v.z * sc.z + sh.z, 0.f);
                    v.w = fmaxf(v.w * sc.w + sh.w, 0.f);
                }
                *(uint2*)(smem + SM2_A + (unsigned)(row * STRD + c4 * 4) * 2) =
                    pack_f16(v);
            }
        } else {
            const uint4* Xh = (const uint4*)((const unsigned short*)g_xh +
                                             (size_t)n0 * FDIM);
            copy_t64(sb + SM2_A, Xh, tid);
            CPA_COMMIT();
        }
        CPA_WAIT0();
        __syncthreads();

        mma_pass64(sb + SM2_A, sb + SM2_BH, acc, wm, wn, lid);
        mma_pass64(sb + SM2_A, sb + SM2_BL, acc, wm, wn, lid);
    }
    __syncthreads();

    float* E = (float*)smem;   // 64 x EPI_LD fp32 (33792 B)
#pragma unroll
    for (int mf = 0; mf < 2; mf++)
#pragma unroll
        for (int nf = 0; nf < 4; nf++) {
            int row = wm * 32 + mf * 16 + g;
            int col = wn * 32 + nf * 8 + tg * 2;
            *(float2*)(E + row * EPI_LD + col) =
                make_float2(acc[mf][nf][0], acc[mf][nf][1]);
            *(float2*)(E + (row + 8) * EPI_LD + col) =
                make_float2(acc[mf][nf][2], acc[mf][nf][3]);
        }
    __syncthreads();

    const int c4 = tid & 31, rg = tid >> 5;
    float4 bias = g_bias[c4];
#pragma unroll
    for (int i = 0; i < 8; i++) {
        int row = i * 8 + rg;
        if (row < valid) {
            float4 v = *(float4*)(E + row * EPI_LD + c4 * 4);
            v.x += bias.x; v.y += bias.y; v.z += bias.z; v.w += bias.w;
            *(float4*)(out + (size_t)(n0 + row) * FDIM + c4 * 4) = v;
        }
    }
}

extern "C" void kernel_launch(void* const* d_in, const int* in_sizes, int n_in,
                              void* d_out, int out_size) {
    const float* x          = (const float*)d_in[0];
    const int*   edge_index = (const int*)d_in[1];   // int32 (JAX x64 disabled)
    const int*   edge_type  = (const int*)d_in[2];
    const float* W_self     = (const float*)d_in[3];
    const float* b_self     = (const float*)d_in[4];
    const float* W1         = (const float*)d_in[5];
    const float* b1         = (const float*)d_in[6];
    const float* gamma      = (const float*)d_in[7];
    const float* beta       = (const float*)d_in[8];
    const float* W2         = (const float*)d_in[9];
    const float* b2         = (const float*)d_in[10];
    float* out = (float*)d_out;

    cudaFuncSetAttribute(k_gemm1, cudaFuncAttributeMaxDynamicSharedMemorySize, SM_TOTAL1);
    cudaFuncSetAttribute(k_gemm2, cudaFuncAttributeMaxDynamicSharedMemorySize, SM_TOTAL2);

    k_prep<<<PREP_TOTAL, NT>>>(W1, W2, W_self, x);
    k_bucket<<<(NE / 4 + 255) / 256, 256>>>(edge_index, edge_type);
    k_gather<<<(NSEG * 32 + 255) / 256, 256>>>(x);
    dim3 g1(NBLK, NREL);
    k_gemm1<<<g1, NT, SM_TOTAL1>>>(b1);
    k_bn<<<1, 512>>>(gamma, beta, b_self, b2);
    k_gemm2<<<NBLK2, NT, SM_TOTAL2>>>(out);
}